// round 13
// baseline (speedup 1.0000x reference)
#include <cuda_runtime.h>
#include <math.h>

// ---------------------------------------------------------------------------
// AvULoss: N=2^21 rows, C=32. Depth-3 cp.async pipeline (dynamic smem,
// 3 x 128-row x 36-float buffers = 55,296 B/block), 128-thread blocks,
// dynamic work-stealing tile queue. Two tiles always in flight per block.
//   y = x*log2e, e = 2^y; S = sum e, dot = sum e*y, emax = max e
//   conf = emax/S ; unc = ln2*(log2 S - dot/S)
//   accurate = (2^(x[lab]*log2e) == emax), x[lab] from the smem tile
//   num = sum w*[accurate==certain], den = sum w
//   loss = -log(num/(den+1e-10) + 1e-10)
// g_next/g_acc/g_ticket reset by the last-ticket block -> graph-replay safe.
// Labels arrive as int32 (JAX x64-disabled downcasts the int64 randint).
// ---------------------------------------------------------------------------

#define BLOCK 128
#define TILE_ROWS 128
#define RSTRIDE 36
#define TILE_FLOATS (TILE_ROWS * RSTRIDE)     // 4608
#define SMEM_BYTES (3 * TILE_FLOATS * 4)      // 55,296
#define GRIDC 592                 // 148 SMs x 4 resident blocks (smem-capped)
#define LOG2E 1.4426950408889634f
#define LN2   0.6931471805599453f

__device__ double g_acc[2];
__device__ unsigned int g_ticket = 0;
__device__ unsigned int g_next = 2 * GRIDC;   // prologue pops 2 tiles/block

__device__ __forceinline__ float tanh_approx(float x) {
    float r;
    asm("tanh.approx.f32 %0, %1;" : "=f"(r) : "f"(x));
    return r;
}
__device__ __forceinline__ void cp_async16(float* smem_dst, const float4* gmem_src) {
    unsigned s;
    asm("{ .reg .u64 t; cvta.to.shared.u64 t, %1; cvt.u32.u64 %0, t; }"
        : "=r"(s) : "l"(smem_dst));
    asm volatile("cp.async.cg.shared.global [%0], [%1], 16;\n"
                 :: "r"(s), "l"(gmem_src) : "memory");
}
__device__ __forceinline__ void cp_commit() {
    asm volatile("cp.async.commit_group;\n" ::: "memory");
}
__device__ __forceinline__ void cp_wait2() {
    asm volatile("cp.async.wait_group 2;\n" ::: "memory");
}

__global__ __launch_bounds__(BLOCK)
void avu_kernel(const float4* __restrict__ logits4,
                const int* __restrict__ labels,
                const float* __restrict__ unc_th_p,
                float* __restrict__ out,
                int numTiles)
{
    extern __shared__ float sbuf[];          // 3 x TILE_FLOATS
    __shared__ float sred[8];
    __shared__ int s_p0, s_p1, s_next;
    __shared__ bool s_last;

    const int tid = threadIdx.x;
    const float th = __ldg(unc_th_p);

    float acc_num = 0.f, acc_den = 0.f;

    // ---- prologue: own tile + two popped tiles into bufs 0,1 (issue 0,1) ----
    int tile = blockIdx.x;                   // grid <= numTiles guaranteed
    {
        const float4* src = logits4 + (size_t)tile * (TILE_ROWS * 8);
#pragma unroll
        for (int k = 0; k < 8; ++k) {
            int i = tid + k * BLOCK;
            int r = i >> 3, c = i & 7;
            cp_async16(&sbuf[0 * TILE_FLOATS + r * RSTRIDE + c * 4], &src[i]);
        }
    }
    cp_commit();                             // group 0 (tile T0)
    if (tid == 0) {
        s_p0 = (int)atomicAdd(&g_next, 1u);
        s_p1 = (int)atomicAdd(&g_next, 1u);
    }
    __syncthreads();
    int n1 = s_p0;
    int n2 = s_p1;
    if (n1 < numTiles) {
        const float4* src = logits4 + (size_t)n1 * (TILE_ROWS * 8);
#pragma unroll
        for (int k = 0; k < 8; ++k) {
            int i = tid + k * BLOCK;
            int r = i >> 3, c = i & 7;
            cp_async16(&sbuf[1 * TILE_FLOATS + r * RSTRIDE + c * 4], &src[i]);
        }
    }
    cp_commit();                             // group 1 (tile T1 = n1)

    int bi = 0;                              // buffer holding current tile

    while (tile < numTiles) {
        // ---- issue T_{k+2} = n2 into buffer (bi+2)%3 ----
        if (n2 < numTiles) {
            int bI = bi + 2; if (bI >= 3) bI -= 3;
            const float4* src = logits4 + (size_t)n2 * (TILE_ROWS * 8);
            float* dst = &sbuf[bI * TILE_FLOATS];
#pragma unroll
            for (int k = 0; k < 8; ++k) {
                int i = tid + k * BLOCK;
                int r = i >> 3, c = i & 7;
                cp_async16(&dst[r * RSTRIDE + c * 4], &src[i]);
            }
        }
        cp_commit();                         // one group per iteration, always
        if (tid == 0) s_next = (int)atomicAdd(&g_next, 1u);   // T_{k+3}

        int lab = labels[(size_t)tile * TILE_ROWS + tid];     // hidden by wait

        cp_wait2();                          // current tile's group complete
        __syncthreads();                     // data + s_next visible

        // ---- thread-per-row compute from buffer bi ----
        const float* rowp = &sbuf[bi * TILE_FLOATS + tid * RSTRIDE];
        float S = 0.f, dot = 0.f, emax = 0.f;
#pragma unroll
        for (int c = 0; c < 8; ++c) {
            float4 v = *(const float4*)&rowp[c * 4];
            float xs[4] = {v.x, v.y, v.z, v.w};
#pragma unroll
            for (int j = 0; j < 4; ++j) {
                float y = xs[j] * LOG2E;
                float e = exp2f(y);
                S += e;
                dot = __fmaf_rn(e, y, dot);
                emax = fmaxf(emax, e);
            }
        }
        float xlab = rowp[lab];

        float invS = __frcp_rn(S);
        float conf = emax * invS;                       // max softmax prob
        float unc  = LN2 * (__log2f(S) - dot * invS);   // predictive entropy
        float elab = exp2f(xlab * LOG2E);
        bool accurate = (elab == emax);
        bool certain  = (unc <= th);
        float t = tanh_approx(unc);
        float w = (accurate ? conf : (1.f - conf)) * (certain ? (1.f - t) : t);
        acc_num += (accurate == certain) ? w : 0.f;     // cats ac + iu
        acc_den += w;

        int n3 = s_next;                     // read before the final barrier
        __syncthreads();                     // all done reading buf bi
        bi = bi + 1; if (bi >= 3) bi -= 3;   // bi's buffer gets reused next iter
        tile = n1; n1 = n2; n2 = n3;
    }

    // ---- block reduction of (num, den), once ----
#pragma unroll
    for (int o = 16; o > 0; o >>= 1) {
        acc_num += __shfl_down_sync(0xffffffffu, acc_num, o);
        acc_den += __shfl_down_sync(0xffffffffu, acc_den, o);
    }
    const int wid = tid >> 5;
    if ((tid & 31) == 0) {
        sred[wid]     = acc_num;
        sred[wid + 4] = acc_den;
    }
    __syncthreads();

    if (tid < 2) {
        double s = 0.0;
#pragma unroll
        for (int wv = 0; wv < 4; ++wv) s += (double)sred[tid * 4 + wv];
        atomicAdd(&g_acc[tid], s);
        __threadfence();
    }
    __syncthreads();

    // ---- last-block finalize + reset (graph-replay deterministic) ----
    if (tid == 0) {
        unsigned int ticket = atomicAdd(&g_ticket, 1u);
        s_last = (ticket == gridDim.x - 1u);
    }
    __syncthreads();
    if (s_last && tid == 0) {
        volatile double* acc = g_acc;
        double nsum = acc[0], dsum = acc[1];
        double avu = nsum / (dsum + 1e-10);
        out[0] = (float)(-log(avu + 1e-10));
        g_acc[0] = 0.0; g_acc[1] = 0.0;
        g_next = 2 * GRIDC;                  // reset the work queue
        __threadfence();
        g_ticket = 0u;
    }
}

extern "C" void kernel_launch(void* const* d_in, const int* in_sizes, int n_in,
                              void* d_out, int out_size)
{
    const float4* logits4 = (const float4*)d_in[0];
    const int*    labels  = (const int*)d_in[1];
    const float*  unc_th  = (const float*)d_in[2];
    float* out = (float*)d_out;

    const int N = in_sizes[1];               // rows (2^21)
    const int numTiles = N / TILE_ROWS;      // 16384

    // Idempotent, host-side, capture-legal: raise the dynamic smem limit.
    cudaFuncSetAttribute(avu_kernel,
                         cudaFuncAttributeMaxDynamicSharedMemorySize,
                         SMEM_BYTES);

    int grid = GRIDC;
    if (grid > numTiles) grid = numTiles;

    avu_kernel<<<grid, BLOCK, SMEM_BYTES>>>(logits4, labels, unc_th, out, numTiles);
}

// round 14
// speedup vs baseline: 1.1215x; 1.1215x over previous
#include <cuda_runtime.h>
#include <math.h>

// ---------------------------------------------------------------------------
// AvULoss: N=2^21 rows, C=32. Depth-2 cp.async pipeline (R10 skeleton) with
// XOR-swizzled 64-row tiles (no padding -> 16KB/buffer) and BLOCK=64 so 13
// blocks (26 warps) fit per SM. Dynamic work-stealing tile queue.
// Swizzle: float4-chunk c of row r lives at chunk (c ^ (r & 7)); conflict-free
// for both the LDGSTS writes and the LDS.128 row reads.
//   y = x*log2e, e = 2^y; S = sum e, dot = sum e*y, emax = max e
//   conf = emax/S ; unc = ln2*(log2 S - dot/S)
//   accurate = (2^(x[lab]*log2e) == emax), x[lab] from the smem tile
//   num = sum w*[accurate==certain], den = sum w
//   loss = -log(num/(den+1e-10) + 1e-10)
// g_next/g_acc/g_ticket reset by the last-ticket block -> graph-replay safe.
// Labels arrive as int32 (JAX x64-disabled downcasts the int64 randint).
// ---------------------------------------------------------------------------

#define BLOCK 64
#define TILE_ROWS 64
#define TILE_FLOATS (TILE_ROWS * 32)      // 2048 floats = 8KB... x4B = 8192B? (64*32*4 = 8192B) per buffer
#define GRIDC 1924                        // 148 SMs x 13 resident blocks
#define LOG2E 1.4426950408889634f
#define LN2   0.6931471805599453f

__device__ double g_acc[2];
__device__ unsigned int g_ticket = 0;
__device__ unsigned int g_next = GRIDC;   // first dynamically-issued tile

__device__ __forceinline__ float tanh_approx(float x) {
    float r;
    asm("tanh.approx.f32 %0, %1;" : "=f"(r) : "f"(x));
    return r;
}
__device__ __forceinline__ void cp_async16(float* smem_dst, const float4* gmem_src) {
    unsigned s;
    asm("{ .reg .u64 t; cvta.to.shared.u64 t, %1; cvt.u32.u64 %0, t; }"
        : "=r"(s) : "l"(smem_dst));
    asm volatile("cp.async.cg.shared.global [%0], [%1], 16;\n"
                 :: "r"(s), "l"(gmem_src) : "memory");
}
__device__ __forceinline__ void cp_commit() {
    asm volatile("cp.async.commit_group;\n" ::: "memory");
}
__device__ __forceinline__ void cp_wait1() {
    asm volatile("cp.async.wait_group 1;\n" ::: "memory");
}

__global__ __launch_bounds__(BLOCK)
void avu_kernel(const float4* __restrict__ logits4,
                const int* __restrict__ labels,
                const float* __restrict__ unc_th_p,
                float* __restrict__ out,
                int numTiles)
{
    __shared__ float sbuf[2][TILE_FLOATS];   // 2 x 8KB, XOR-swizzled rows
    __shared__ float sred[4];                // 2 warps x {num, den}
    __shared__ int s_next;
    __shared__ bool s_last;

    const int tid = threadIdx.x;
    const float th = __ldg(unc_th_p);
    const int rsw = (tid & 7) << 2;          // this row's swizzle (x4 floats)

    float acc_num = 0.f, acc_den = 0.f;
    int buf = 0;

    // ---- prologue: block b owns tile b; grab the first dynamic tile ----
    int tile = blockIdx.x;                   // grid == GRIDC <= numTiles
    {
        const float4* src = logits4 + (size_t)tile * (TILE_ROWS * 8);
#pragma unroll
        for (int k = 0; k < 8; ++k) {
            int i = tid + k * BLOCK;         // float4 index within tile
            int r = i >> 3, c = i & 7;
            int cs = c ^ (r & 7);            // swizzled chunk
            cp_async16(&sbuf[0][r * 32 + cs * 4], &src[i]);
        }
    }
    cp_commit();
    if (tid == 0) s_next = (int)atomicAdd(&g_next, 1u);
    __syncthreads();
    int nxt = s_next;

    while (tile < numTiles) {
        // ---- prefetch the next tile (if any) into the other buffer ----
        if (nxt < numTiles) {
            const float4* src = logits4 + (size_t)nxt * (TILE_ROWS * 8);
#pragma unroll
            for (int k = 0; k < 8; ++k) {
                int i = tid + k * BLOCK;
                int r = i >> 3, c = i & 7;
                int cs = c ^ (r & 7);
                cp_async16(&sbuf[buf ^ 1][r * 32 + cs * 4], &src[i]);
            }
        }
        cp_commit();
        if (tid == 0) s_next = (int)atomicAdd(&g_next, 1u);   // for iter+2

        int lab = labels[(size_t)tile * TILE_ROWS + tid];     // hidden by wait

        cp_wait1();                          // current tile's group complete
        __syncthreads();                     // data + s_next visible

        // ---- thread-per-row compute (row = tid, swizzled chunks) ----
        const float* rowp = &sbuf[buf][tid * 32];
        float S = 0.f, dot = 0.f, emax = 0.f;
#pragma unroll
        for (int c = 0; c < 8; ++c) {
            float4 v = *(const float4*)&rowp[(c << 2) ^ rsw];
            float xs[4] = {v.x, v.y, v.z, v.w};
#pragma unroll
            for (int j = 0; j < 4; ++j) {
                float y = xs[j] * LOG2E;
                float e = exp2f(y);
                S += e;
                dot = __fmaf_rn(e, y, dot);
                emax = fmaxf(emax, e);
            }
        }
        float xlab = rowp[(((lab >> 2) << 2) ^ rsw) + (lab & 3)];

        float invS = __frcp_rn(S);
        float conf = emax * invS;                       // max softmax prob
        float unc  = LN2 * (__log2f(S) - dot * invS);   // predictive entropy
        float elab = exp2f(xlab * LOG2E);
        bool accurate = (elab == emax);
        bool certain  = (unc <= th);
        float t = tanh_approx(unc);
        float w = (accurate ? conf : (1.f - conf)) * (certain ? (1.f - t) : t);
        acc_num += (accurate == certain) ? w : 0.f;     // cats ac + iu
        acc_den += w;

        int nxt_new = s_next;                // read before the final barrier
        __syncthreads();                     // all done reading buf before reuse
        buf ^= 1;
        tile = nxt;
        nxt = nxt_new;
    }

    // ---- block reduction of (num, den), once ----
#pragma unroll
    for (int o = 16; o > 0; o >>= 1) {
        acc_num += __shfl_down_sync(0xffffffffu, acc_num, o);
        acc_den += __shfl_down_sync(0xffffffffu, acc_den, o);
    }
    const int wid = tid >> 5;
    if ((tid & 31) == 0) {
        sred[wid]     = acc_num;
        sred[wid + 2] = acc_den;
    }
    __syncthreads();

    if (tid < 2) {
        double s = (double)sred[tid * 2] + (double)sred[tid * 2 + 1];
        atomicAdd(&g_acc[tid], s);
        __threadfence();
    }
    __syncthreads();

    // ---- last-block finalize + reset (graph-replay deterministic) ----
    if (tid == 0) {
        unsigned int ticket = atomicAdd(&g_ticket, 1u);
        s_last = (ticket == gridDim.x - 1u);
    }
    __syncthreads();
    if (s_last && tid == 0) {
        volatile double* acc = g_acc;
        double nsum = acc[0], dsum = acc[1];
        double avu = nsum / (dsum + 1e-10);
        out[0] = (float)(-log(avu + 1e-10));
        g_acc[0] = 0.0; g_acc[1] = 0.0;
        g_next = GRIDC;                      // reset the work queue
        __threadfence();
        g_ticket = 0u;
    }
}

extern "C" void kernel_launch(void* const* d_in, const int* in_sizes, int n_in,
                              void* d_out, int out_size)
{
    const float4* logits4 = (const float4*)d_in[0];
    const int*    labels  = (const int*)d_in[1];
    const float*  unc_th  = (const float*)d_in[2];
    float* out = (float*)d_out;

    const int N = in_sizes[1];               // rows (2^21)
    const int numTiles = N / TILE_ROWS;      // 32768

    avu_kernel<<<GRIDC, BLOCK>>>(logits4, labels, unc_th, out, numTiles);
}